// round 1
// baseline (speedup 1.0000x reference)
#include <cuda_runtime.h>
#include <cuda_bf16.h>

// Problem constants
#define B    32
#define LQ   32
#define DLEN 4096
#define P    16
#define D    2048
#define H    2048

#define NCHUNK 8            // token chunks per batch in scoring kernel
#define KSPLIT 8            // k-split for skinny GEMMs
#define TILE_N 64
#define KB     64

// ---------------- scratch (device globals; no allocation allowed) ----------------
__device__ float g_qrep[B * D];
__device__ float g_qenc[B * H];
__device__ float g_v[B * D];
__device__ float g_part[KSPLIT * B * 2048];      // GEMM partials (2 MB)
__device__ float g_c[B];
__device__ float g_sacc[B * NCHUNK * P];         // score partials

// ---------------- Phase A1: q_rep = masked mean of query token embeddings ----------------
__global__ void k_qrep(const int* __restrict__ queries,
                       const int* __restrict__ qlen,
                       const float* __restrict__ emb) {
    int b = blockIdx.x;
    __shared__ int toks[LQ];
    int len;
    if (threadIdx.x < LQ) toks[threadIdx.x] = queries[b * LQ + threadIdx.x];
    len = qlen[b];
    __syncthreads();
    float inv = 1.0f / (float)len;
    for (int d = threadIdx.x; d < D; d += blockDim.x) {
        float s = 0.0f;
        for (int l = 0; l < len; l++) {
            s += emb[(size_t)toks[l] * D + d];
        }
        g_qrep[b * D + d] = s * inv;
    }
}

// ---------------- Phase A2: skinny GEMM  C[32,2048] = A[32,2048] x W (optionally transposed) ----
// transW==0:  C[b,n] = sum_k A[b,k] * W[n*2048 + k]   (q_enc = q_rep @ W.T)
// transW==1:  C[b,n] = sum_k A[b,k] * W[k*2048 + n]   (v     = q_enc @ W)
// grid: (2048/TILE_N = 32, KSPLIT = 8); each block covers k-range of 2048/KSPLIT = 256.
// Writes per-split partials to g_part (disjoint -> deterministic, no atomics).
__global__ void k_gemm(const float* __restrict__ A,
                       const float* __restrict__ W,
                       int transW) {
    const int n0 = blockIdx.x * TILE_N;
    const int k0 = blockIdx.y * (2048 / KSPLIT);
    __shared__ float As[32][KB];
    __shared__ float Ws[TILE_N][KB + 1];   // +1 pad: conflict-free

    const int t  = threadIdx.x;      // 256 threads
    const int tb = t >> 5;           // 0..7 -> rows b = tb*4 .. tb*4+3
    const int tn = t & 31;           // cols n0+tn, n0+tn+32

    float acc00 = 0.f, acc01 = 0.f, acc10 = 0.f, acc11 = 0.f;
    float acc20 = 0.f, acc21 = 0.f, acc30 = 0.f, acc31 = 0.f;

    for (int kc = 0; kc < (2048 / KSPLIT); kc += KB) {
        const int kbase = k0 + kc;
        // load A tile [32 x KB] = 2048 floats
        #pragma unroll
        for (int i = 0; i < 8; i++) {
            int flat = t + i * 256;
            int bb = flat >> 6, kk = flat & 63;
            As[bb][kk] = A[bb * 2048 + kbase + kk];
        }
        // load W tile [TILE_N x KB] = 4096 floats
        if (!transW) {
            #pragma unroll
            for (int i = 0; i < 16; i++) {
                int flat = t + i * 256;
                int nn = flat >> 6, kk = flat & 63;
                Ws[nn][kk] = W[(size_t)(n0 + nn) * 2048 + kbase + kk];
            }
        } else {
            #pragma unroll
            for (int i = 0; i < 16; i++) {
                int flat = t + i * 256;
                int nn = flat & 63, kk = flat >> 6;
                Ws[nn][kk] = W[(size_t)(kbase + kk) * 2048 + n0 + nn];
            }
        }
        __syncthreads();

        #pragma unroll 16
        for (int k = 0; k < KB; k++) {
            float a0 = As[tb * 4 + 0][k];
            float a1 = As[tb * 4 + 1][k];
            float a2 = As[tb * 4 + 2][k];
            float a3 = As[tb * 4 + 3][k];
            float w0 = Ws[tn][k];
            float w1 = Ws[tn + 32][k];
            acc00 += a0 * w0; acc01 += a0 * w1;
            acc10 += a1 * w0; acc11 += a1 * w1;
            acc20 += a2 * w0; acc21 += a2 * w1;
            acc30 += a3 * w0; acc31 += a3 * w1;
        }
        __syncthreads();
    }

    float* out = g_part + (size_t)blockIdx.y * 32 * 2048;
    out[(tb * 4 + 0) * 2048 + n0 + tn]      = acc00;
    out[(tb * 4 + 0) * 2048 + n0 + tn + 32] = acc01;
    out[(tb * 4 + 1) * 2048 + n0 + tn]      = acc10;
    out[(tb * 4 + 1) * 2048 + n0 + tn + 32] = acc11;
    out[(tb * 4 + 2) * 2048 + n0 + tn]      = acc20;
    out[(tb * 4 + 2) * 2048 + n0 + tn + 32] = acc21;
    out[(tb * 4 + 3) * 2048 + n0 + tn]      = acc30;
    out[(tb * 4 + 3) * 2048 + n0 + tn + 32] = acc31;
}

// reduce the KSPLIT partials; optionally add bias (for q_enc)
__global__ void k_reduce(float* __restrict__ C,
                         const float* __restrict__ bias,
                         int addBias) {
    int idx = blockIdx.x * 256 + threadIdx.x;   // 65536 elements
    float s = 0.0f;
    #pragma unroll
    for (int sp = 0; sp < KSPLIT; sp++) s += g_part[sp * 65536 + idx];
    if (addBias) s += bias[idx & 2047];
    C[idx] = s;
}

// c[b] = q_enc[b] . bias
__global__ void k_qc(const float* __restrict__ bias) {
    int b = blockIdx.x;
    float s = 0.0f;
    for (int i = threadIdx.x; i < H; i += 256) s += g_qenc[b * H + i] * bias[i];
    __shared__ float red[256];
    red[threadIdx.x] = s;
    __syncthreads();
    for (int o = 128; o; o >>= 1) {
        if (threadIdx.x < o) red[threadIdx.x] += red[threadIdx.x + o];
        __syncthreads();
    }
    if (threadIdx.x == 0) g_c[b] = red[0];
}

// ---------------- Phase B: per-token gather-dot + segment accumulation ----------------
// grid (B, NCHUNK); block = 256 threads = 8 warps; one warp per token.
__global__ void k_score(const int* __restrict__ docs,
                        const int* __restrict__ plen,
                        const float* __restrict__ emb) {
    const int b = blockIdx.x;
    const int chunk = blockIdx.y;
    __shared__ float vs[D];
    __shared__ int cum[P];
    __shared__ float warp_acc[8][P];

    const int t = threadIdx.x;
    const int w = t >> 5;
    const int lane = t & 31;

    for (int i = t; i < D; i += 256) vs[i] = g_v[b * D + i];
    if (t == 0) {
        int c0 = 0;
        #pragma unroll
        for (int p = 0; p < P; p++) { c0 += plen[b * P + p]; cum[p] = c0; }
    }
    if (lane < P) warp_acc[w][lane] = 0.0f;
    __syncthreads();

    const int total = cum[P - 1];
    const int tchunk = DLEN / NCHUNK;   // 512
    const int tstart = chunk * tchunk;
    int tend = tstart + tchunk;
    if (tend > DLEN) tend = DLEN;

    const float4* vv = (const float4*)vs;

    for (int tok = tstart + w; tok < tend; tok += 8) {
        if (tok >= total) break;    // warp-uniform, monotonically increasing
        int id = docs[b * DLEN + tok];
        int seg = 0;
        #pragma unroll
        for (int p = 0; p < P; p++) seg += (tok >= cum[p]) ? 1 : 0;

        const float4* row = (const float4*)(emb + (size_t)id * D);
        float s = 0.0f;
        #pragma unroll
        for (int i = 0; i < 16; i++) {
            float4 e = row[lane + i * 32];
            float4 x = vv[lane + i * 32];
            s += e.x * x.x + e.y * x.y + e.z * x.z + e.w * x.w;
        }
        #pragma unroll
        for (int o = 16; o; o >>= 1) s += __shfl_xor_sync(0xFFFFFFFFu, s, o);
        if (lane == 0) warp_acc[w][seg] += s;   // single writer per row -> deterministic
    }
    __syncthreads();

    if (t < P) {
        float r = 0.0f;
        #pragma unroll
        for (int ww = 0; ww < 8; ww++) r += warp_acc[ww][t];
        g_sacc[(b * NCHUNK + chunk) * P + t] = r;
    }
}

// ---------------- final: combine chunk partials, divide, add c, mask ----------------
__global__ void k_final(const int* __restrict__ plen, float* __restrict__ out) {
    int i = threadIdx.x;                 // 512 = B*P
    int b = i >> 4, p = i & 15;
    float s = 0.0f;
    #pragma unroll
    for (int ch = 0; ch < NCHUNK; ch++) s += g_sacc[(b * NCHUNK + ch) * P + p];
    int len = plen[b * P + p];
    float denom = (float)(len > 0 ? len : 1);
    float val = s / denom + g_c[b];
    out[i] = (len > 0) ? val : 0.0f;
    (void)p;
}

// ---------------- launch ----------------
extern "C" void kernel_launch(void* const* d_in, const int* in_sizes, int n_in,
                              void* d_out, int out_size) {
    const int*   queries = (const int*)d_in[0];
    const int*   qlen    = (const int*)d_in[1];
    const int*   docs    = (const int*)d_in[2];
    const int*   plen    = (const int*)d_in[3];
    const float* emb     = (const float*)d_in[4];
    const float* W       = (const float*)d_in[5];
    const float* bias    = (const float*)d_in[6];
    float*       out     = (float*)d_out;

    // resolve device symbol addresses for pointer-parameter kernels
    float *qrep_p, *qenc_p, *v_p;
    cudaGetSymbolAddress((void**)&qrep_p, g_qrep);
    cudaGetSymbolAddress((void**)&qenc_p, g_qenc);
    cudaGetSymbolAddress((void**)&v_p, g_v);

    k_qrep<<<B, 256>>>(queries, qlen, emb);
    k_gemm<<<dim3(2048 / TILE_N, KSPLIT), 256>>>(qrep_p, W, 0);
    k_reduce<<<256, 256>>>(qenc_p, bias, 1);
    k_gemm<<<dim3(2048 / TILE_N, KSPLIT), 256>>>(qenc_p, W, 1);
    k_reduce<<<256, 256>>>(v_p, bias, 0);
    k_qc<<<B, 256>>>(bias);
    k_score<<<dim3(B, NCHUNK), 256>>>(docs, plen, emb);
    k_final<<<1, B * P>>>(plen, out);
}

// round 2
// speedup vs baseline: 1.3766x; 1.3766x over previous
#include <cuda_runtime.h>
#include <cuda_bf16.h>

// Problem constants
#define B    32
#define LQ   32
#define DLEN 4096
#define P    16
#define D    2048
#define H    2048

#define KSPLIT 16           // k-split for skinny GEMMs
#define TILE_N 64
#define KB     64

// ---------------- scratch (device globals; no allocation allowed) ----------------
__device__ float g_qrep[B * D];
__device__ float g_qenc[B * H];
__device__ float g_v[B * D];
__device__ float g_part[KSPLIT * B * 2048];      // GEMM partials (4 MB)
__device__ float g_c[B];
__device__ float g_psum[2 * B * P * D];          // passage embedding sums (8 MB)

// ---------------- q_rep = masked mean of query token embeddings ----------------
// grid (B, 8): block handles 256 d's; one d per thread.
__global__ void k_qrep(const int* __restrict__ queries,
                       const int* __restrict__ qlen,
                       const float* __restrict__ emb) {
    int b = blockIdx.x;
    __shared__ int toks[LQ];
    if (threadIdx.x < LQ) toks[threadIdx.x] = queries[b * LQ + threadIdx.x];
    int len = qlen[b];
    __syncthreads();
    float inv = 1.0f / (float)len;
    int d = blockIdx.y * 256 + threadIdx.x;
    float s = 0.0f;
    for (int l = 0; l < len; l++) s += emb[(size_t)toks[l] * D + d];
    g_qrep[b * D + d] = s * inv;
}

// ---------------- skinny GEMM  C[32,2048] = A[32,2048] x W (optionally transposed) ----
// transW==0:  C[b,n] = sum_k A[b,k] * W[n*2048 + k]
// transW==1:  C[b,n] = sum_k A[b,k] * W[k*2048 + n]
// grid (32, KSPLIT); per-split partials -> deterministic, no atomics.
__global__ void k_gemm(const float* __restrict__ A,
                       const float* __restrict__ W,
                       int transW) {
    const int n0 = blockIdx.x * TILE_N;
    const int k0 = blockIdx.y * (2048 / KSPLIT);
    __shared__ float As[32][KB];
    __shared__ float Ws[TILE_N][KB + 1];

    const int t  = threadIdx.x;      // 256 threads
    const int tb = t >> 5;
    const int tn = t & 31;

    float acc00 = 0.f, acc01 = 0.f, acc10 = 0.f, acc11 = 0.f;
    float acc20 = 0.f, acc21 = 0.f, acc30 = 0.f, acc31 = 0.f;

    for (int kc = 0; kc < (2048 / KSPLIT); kc += KB) {
        const int kbase = k0 + kc;
        #pragma unroll
        for (int i = 0; i < 8; i++) {
            int flat = t + i * 256;
            int bb = flat >> 6, kk = flat & 63;
            As[bb][kk] = A[bb * 2048 + kbase + kk];
        }
        if (!transW) {
            #pragma unroll
            for (int i = 0; i < 16; i++) {
                int flat = t + i * 256;
                int nn = flat >> 6, kk = flat & 63;
                Ws[nn][kk] = W[(size_t)(n0 + nn) * 2048 + kbase + kk];
            }
        } else {
            #pragma unroll
            for (int i = 0; i < 16; i++) {
                int flat = t + i * 256;
                int nn = flat & 63, kk = flat >> 6;
                Ws[nn][kk] = W[(size_t)(kbase + kk) * 2048 + n0 + nn];
            }
        }
        __syncthreads();

        #pragma unroll 16
        for (int k = 0; k < KB; k++) {
            float a0 = As[tb * 4 + 0][k];
            float a1 = As[tb * 4 + 1][k];
            float a2 = As[tb * 4 + 2][k];
            float a3 = As[tb * 4 + 3][k];
            float w0 = Ws[tn][k];
            float w1 = Ws[tn + 32][k];
            acc00 += a0 * w0; acc01 += a0 * w1;
            acc10 += a1 * w0; acc11 += a1 * w1;
            acc20 += a2 * w0; acc21 += a2 * w1;
            acc30 += a3 * w0; acc31 += a3 * w1;
        }
        __syncthreads();
    }

    float* out = g_part + (size_t)blockIdx.y * 32 * 2048;
    out[(tb * 4 + 0) * 2048 + n0 + tn]      = acc00;
    out[(tb * 4 + 0) * 2048 + n0 + tn + 32] = acc01;
    out[(tb * 4 + 1) * 2048 + n0 + tn]      = acc10;
    out[(tb * 4 + 1) * 2048 + n0 + tn + 32] = acc11;
    out[(tb * 4 + 2) * 2048 + n0 + tn]      = acc20;
    out[(tb * 4 + 2) * 2048 + n0 + tn + 32] = acc21;
    out[(tb * 4 + 3) * 2048 + n0 + tn]      = acc30;
    out[(tb * 4 + 3) * 2048 + n0 + tn + 32] = acc31;
}

__global__ void k_reduce(float* __restrict__ C,
                         const float* __restrict__ bias,
                         int addBias) {
    int idx = blockIdx.x * 256 + threadIdx.x;   // 65536 elements
    float s = 0.0f;
    #pragma unroll
    for (int sp = 0; sp < KSPLIT; sp++) s += g_part[sp * 65536 + idx];
    if (addBias) s += bias[idx & 2047];
    C[idx] = s;
}

// c[b] = q_enc[b] . bias
__global__ void k_qc(const float* __restrict__ bias) {
    int b = blockIdx.x;
    float s = 0.0f;
    for (int i = threadIdx.x; i < H; i += 256) s += g_qenc[b * H + i] * bias[i];
    __shared__ float red[256];
    red[threadIdx.x] = s;
    __syncthreads();
    for (int o = 128; o; o >>= 1) {
        if (threadIdx.x < o) red[threadIdx.x] += red[threadIdx.x + o];
        __syncthreads();
    }
    if (threadIdx.x == 0) g_c[b] = red[0];
}

// ---------------- passage embedding sums (independent of GEMM chain) ----------------
// grid (B, P, 2); block sums its half-passage's emb rows into [D] accumulator.
__global__ void k_psum(const int* __restrict__ docs,
                       const int* __restrict__ plen,
                       const float* __restrict__ emb) {
    const int b = blockIdx.x, p = blockIdx.y, h = blockIdx.z;
    const int t = threadIdx.x;

    __shared__ int toks[130];
    __shared__ int info[2];          // hstart, hn

    if (t == 0) {
        int start = 0;
        for (int q = 0; q < p; q++) start += plen[b * P + q];
        int len = plen[b * P + p];
        int h0 = (len + 1) >> 1;
        info[0] = start + (h ? h0 : 0);
        info[1] = h ? (len - h0) : h0;
    }
    __syncthreads();
    const int hstart = info[0];
    const int nt = info[1];
    if (t < nt) toks[t] = docs[b * DLEN + hstart + t];
    __syncthreads();

    float4 acc0 = make_float4(0.f, 0.f, 0.f, 0.f);
    float4 acc1 = make_float4(0.f, 0.f, 0.f, 0.f);

    int tk = 0;
    for (; tk + 2 <= nt; tk += 2) {
        const float4* r0 = (const float4*)(emb + (size_t)toks[tk] * D);
        const float4* r1 = (const float4*)(emb + (size_t)toks[tk + 1] * D);
        float4 a = r0[t], bb = r0[t + 256];
        float4 c = r1[t], dd = r1[t + 256];
        acc0.x += a.x; acc0.y += a.y; acc0.z += a.z; acc0.w += a.w;
        acc1.x += bb.x; acc1.y += bb.y; acc1.z += bb.z; acc1.w += bb.w;
        acc0.x += c.x; acc0.y += c.y; acc0.z += c.z; acc0.w += c.w;
        acc1.x += dd.x; acc1.y += dd.y; acc1.z += dd.z; acc1.w += dd.w;
    }
    if (tk < nt) {
        const float4* r0 = (const float4*)(emb + (size_t)toks[tk] * D);
        float4 a = r0[t], bb = r0[t + 256];
        acc0.x += a.x; acc0.y += a.y; acc0.z += a.z; acc0.w += a.w;
        acc1.x += bb.x; acc1.y += bb.y; acc1.z += bb.z; acc1.w += bb.w;
    }

    float4* out = (float4*)(g_psum + ((size_t)h * B * P + b * P + p) * D);
    out[t]       = acc0;
    out[t + 256] = acc1;
}

// ---------------- final: score[b,p] = (psum . v[b]) / len + c[b], masked ----------------
__global__ void k_dot(const int* __restrict__ plen, float* __restrict__ out) {
    const int bp = blockIdx.x;            // 512 blocks
    const int b = bp >> 4, p = bp & 15;
    const int t = threadIdx.x;

    const float* s0 = g_psum + (size_t)(b * P + p) * D;
    const float* s1 = g_psum + (size_t)(B * P + b * P + p) * D;
    const float* v  = g_v + b * D;

    float s = 0.0f;
    #pragma unroll
    for (int i = 0; i < 8; i++) {
        int d = t + i * 256;
        s += (s0[d] + s1[d]) * v[d];
    }
    __shared__ float red[256];
    red[t] = s;
    __syncthreads();
    for (int o = 128; o; o >>= 1) {
        if (t < o) red[t] += red[t + o];
        __syncthreads();
    }
    if (t == 0) {
        int len = plen[b * P + p];
        float denom = (float)(len > 0 ? len : 1);
        out[bp] = (len > 0) ? (red[0] / denom + g_c[b]) : 0.0f;
    }
}

// ---------------- launch: fork-join so the gather overlaps the GEMM chain ----------------
extern "C" void kernel_launch(void* const* d_in, const int* in_sizes, int n_in,
                              void* d_out, int out_size) {
    const int*   queries = (const int*)d_in[0];
    const int*   qlen    = (const int*)d_in[1];
    const int*   docs    = (const int*)d_in[2];
    const int*   plen    = (const int*)d_in[3];
    const float* emb     = (const float*)d_in[4];
    const float* W       = (const float*)d_in[5];
    const float* bias    = (const float*)d_in[6];
    float*       out     = (float*)d_out;

    float *qrep_p, *qenc_p, *v_p;
    cudaGetSymbolAddress((void**)&qrep_p, g_qrep);
    cudaGetSymbolAddress((void**)&qenc_p, g_qenc);
    cudaGetSymbolAddress((void**)&v_p, g_v);

    cudaStream_t s2;
    cudaStreamCreateWithFlags(&s2, cudaStreamNonBlocking);
    cudaEvent_t ef, ej;
    cudaEventCreateWithFlags(&ef, cudaEventDisableTiming);
    cudaEventCreateWithFlags(&ej, cudaEventDisableTiming);

    // fork: gather runs on s2 concurrently with the GEMM chain on the main stream
    cudaEventRecord(ef, 0);
    cudaStreamWaitEvent(s2, ef, 0);
    k_psum<<<dim3(B, P, 2), 256, 0, s2>>>(docs, plen, emb);

    k_qrep<<<dim3(B, 8), 256>>>(queries, qlen, emb);
    k_gemm<<<dim3(2048 / TILE_N, KSPLIT), 256>>>(qrep_p, W, 0);
    k_reduce<<<256, 256>>>(qenc_p, bias, 1);
    k_gemm<<<dim3(2048 / TILE_N, KSPLIT), 256>>>(qenc_p, W, 1);
    k_reduce<<<256, 256>>>(v_p, bias, 0);
    k_qc<<<B, 256>>>(bias);

    // join
    cudaEventRecord(ej, s2);
    cudaStreamWaitEvent(0, ej, 0);
    k_dot<<<B * P, 256>>>(plen, out);
}